// round 11
// baseline (speedup 1.0000x reference)
#include <cuda_runtime.h>
#include <cuda_bf16.h>
#include <stdint.h>
#include <math.h>

// Problem: gramBatch [B=8, C=8, N=1024, 16,16] fp32 -> out [8,1024,1024] fp32.
// out[b,i,j] = mean_c (sq_i + sq_j - 2*dot_c(i,j)) * rn_i * rn_j,
//   sq = sum_d g^2, rn = 1/sqrt(sum_d g^4).
// GEMM: pre-scale rows by rn (bf16); accumulate all c and K in fp32 registers
// via mma.sync m16n8k16 bf16. Rank-16 additive term stays fp32 in epilogue.
// R9->R10: 512-thread CTA, 16 warps of 32x32, fragment double-buffering
// (fits the 128-reg cap now that acc is 32 regs). Same barrier-free 3-slot
// cp.async.bulk + mbarrier ring; empty barriers count 16 warps.

#define BB 8
#define CC 8
#define NN 1024
#define DD 256

// Blocked bf16: block index (bc*8 + tile)*4 + kq, each 16KB (128 rows x 128B, swizzled).
__device__ __align__(1024) unsigned char g_bfb[(size_t)BB * CC * 8 * 4 * 16384];
__device__ float g_u[BB * CC * NN]; // sq * rn
__device__ float g_r[BB * CC * NN]; // rn

// ---------------------------------------------------------------------------
// Prep: per-row reductions + bf16 pre-scaled rows in blocked swizzled layout.
// ---------------------------------------------------------------------------
__global__ void prep_kernel(const float* __restrict__ g) {
    int row = blockIdx.x * 8 + threadIdx.y;       // 0..65535
    int lane = threadIdx.x;
    const float* p = g + (size_t)row * DD + lane * 8;
    float4 v0 = *(const float4*)(p);
    float4 v1 = *(const float4*)(p + 4);
    float vals[8] = {v0.x, v0.y, v0.z, v0.w, v1.x, v1.y, v1.z, v1.w};
    float s2 = 0.f, s4 = 0.f;
#pragma unroll
    for (int i = 0; i < 8; ++i) { float q = vals[i] * vals[i]; s2 += q; s4 += q * q; }
#pragma unroll
    for (int o = 16; o > 0; o >>= 1) {
        s2 += __shfl_xor_sync(0xFFFFFFFFu, s2, o);
        s4 += __shfl_xor_sync(0xFFFFFFFFu, s4, o);
    }
    float rn = 1.0f / sqrtf(s4);
    if (lane == 0) { g_u[row] = s2 * rn; g_r[row] = rn; }

    uint32_t w[4];
#pragma unroll
    for (int q = 0; q < 4; ++q) {
        __nv_bfloat162 h = __floats2bfloat162_rn(vals[2 * q] * rn, vals[2 * q + 1] * rn);
        w[q] = *(uint32_t*)&h;
    }
    int bc = row >> 10, n = row & (NN - 1);
    int tile = n >> 7, r = n & 127;
    int kq = lane >> 3, q = lane & 7;             // k-quarter (64 elems = 128B)
    uint32_t off = (uint32_t)(r * 128 + ((q * 16) ^ ((r & 7) * 16)));
    *(uint4*)(g_bfb + (((size_t)(bc * 8 + tile) * 4 + kq) << 14) + off) =
        make_uint4(w[0], w[1], w[2], w[3]);
}

// ---------------------------------------------------------------------------
// Helpers
// ---------------------------------------------------------------------------
__device__ __forceinline__ void ldsm_x4(uint32_t* r, uint32_t a) {
    asm volatile("ldmatrix.sync.aligned.m8n8.x4.shared.b16 {%0,%1,%2,%3}, [%4];"
        : "=r"(r[0]), "=r"(r[1]), "=r"(r[2]), "=r"(r[3]) : "r"(a));
}
__device__ __forceinline__ void mma16816(float* d, const uint32_t* a, uint32_t b0, uint32_t b1) {
    asm volatile("mma.sync.aligned.m16n8k16.row.col.f32.bf16.bf16.f32 "
        "{%0,%1,%2,%3}, {%4,%5,%6,%7}, {%8,%9}, {%0,%1,%2,%3};"
        : "+f"(d[0]), "+f"(d[1]), "+f"(d[2]), "+f"(d[3])
        : "r"(a[0]), "r"(a[1]), "r"(a[2]), "r"(a[3]), "r"(b0), "r"(b1));
}
#define MBAR_INIT(a, n) \
    asm volatile("mbarrier.init.shared.b64 [%0], %1;" :: "r"(a), "r"(n) : "memory")
#define MBAR_EXPECT_TX(a, n) \
    asm volatile("mbarrier.arrive.expect_tx.shared.b64 _, [%0], %1;" :: "r"(a), "r"(n) : "memory")
#define MBAR_ARRIVE(a) \
    asm volatile("mbarrier.arrive.shared.b64 _, [%0];" :: "r"(a) : "memory")
#define MBAR_WAIT(a, ph) do { \
    uint32_t _m = (a); uint32_t _p = (ph); uint32_t _done; \
    asm volatile("{\n\t.reg .pred p;\n\t" \
        "mbarrier.try_wait.parity.acquire.cta.shared::cta.b64 p, [%1], %2;\n\t" \
        "selp.b32 %0, 1, 0, p;\n\t}" : "=r"(_done) : "r"(_m), "r"(_p) : "memory"); \
    if (!_done) { \
        asm volatile("{\n\t.reg .pred P1;\n\t" \
            "WL_%=:\n\t" \
            "mbarrier.try_wait.parity.acquire.cta.shared::cta.b64 P1, [%0], %1, 0x989680;\n\t" \
            "@P1 bra.uni WD_%=;\n\t" \
            "bra.uni WL_%=;\n\t" \
            "WD_%=:\n\t}" :: "r"(_m), "r"(_p) : "memory"); \
    } \
} while (0)
#define BULK_CP(dst, src, nbytes, mb) \
    asm volatile("cp.async.bulk.shared::cta.global.mbarrier::complete_tx::bytes [%0], [%1], %2, [%3];" \
        :: "r"(dst), "l"(src), "r"(nbytes), "r"(mb) : "memory")

// ---------------------------------------------------------------------------
// Main: per (tile-pair, b) CTA; 16 warps (4x4), warp tile 32x32.
// 32 chunks (8c x 4 k-quarters of 64), 3-slot mbarrier ring fed by thread 0
// with cp.async.bulk; fragment double-buffering inside each chunk.
// ---------------------------------------------------------------------------
__global__ __launch_bounds__(512, 1)
void gram_mma_kernel(float* __restrict__ out) {
    extern __shared__ unsigned char S[];
    uint32_t sbase;
    asm("{ .reg .u64 t; cvta.to.shared.u64 t, %1; cvt.u32.u64 %0, t; }"
        : "=r"(sbase) : "l"(S));

    float2* pA = (float2*)S;                   // [8][128] (u_a, r_a)  8KB
    float2* qB = (float2*)(S + 8192);          // [8][128] (r_b, u_b)  8KB
    const uint32_t TILES = sbase + 16384;      // 3 slots x (A 16KB + B 16KB)
    float* outT = (float*)(S + 16384);         // reused after GEMM: [128][130]
    const uint32_t MB = sbase + 16384 + 98304; // 6 mbarriers (48B)
    // full[s] = MB + s*8 ; empty[s] = MB + 24 + s*8

    int tid = threadIdx.x, lane = tid & 31, wid = tid >> 5;
    int warp_m = wid >> 2, warp_n = wid & 3;   // 4x4 warp grid
    int pair = blockIdx.x, b = blockIdx.y;
    int it = 0, rem = pair;
    while (rem >= 8 - it) { rem -= 8 - it; ++it; }
    int jt = it + rem;

    if (tid == 0) {
#pragma unroll
        for (int s = 0; s < 3; ++s) { MBAR_INIT(MB + s * 8, 1u); MBAR_INIT(MB + 24 + s * 8, 16u); }
    }

    // Epilogue scalars into smem.
    for (int idx = tid; idx < 1024; idx += 512) {
        int c = idx >> 7, i = idx & 127;
        int ra = (b * CC + c) * NN + it * 128 + i;
        int rb = (b * CC + c) * NN + jt * 128 + i;
        pA[idx] = make_float2(g_u[ra], g_r[ra]);
        qB[idx] = make_float2(g_r[rb], g_u[rb]);
    }
    __syncthreads();   // mbarrier init + scalars visible

    // Block index = b*256 + c*32 + tile*4 + kq  (x16KB each).
    const size_t blkA0 = (size_t)(b * 256 + it * 4) << 14;
    const size_t blkB0 = (size_t)(b * 256 + jt * 4) << 14;

    // chunk ch: c = ch>>2, kq = ch&3.
    auto produce = [&](int ch, int slot) {
        int c = ch >> 2, kq = ch & 3;
        size_t boff = ((size_t)(c * 32 + kq)) << 14;
        uint32_t mb = MB + (uint32_t)slot * 8;
        uint32_t dA = TILES + (uint32_t)slot * 32768u;
        MBAR_EXPECT_TX(mb, 32768u);
        BULK_CP(dA, (const void*)(g_bfb + blkA0 + boff), 16384u, mb);
        BULK_CP(dA + 16384u, (const void*)(g_bfb + blkB0 + boff), 16384u, mb);
    };

    if (tid == 0) { produce(0, 0); produce(1, 1); produce(2, 2); }

    // Fragment addressing (per-lane constants). Rows are 128B (k64).
    int arow = warp_m * 32 + (lane & 15);
    uint32_t aBase = (uint32_t)(arow * 128);
    uint32_t aXor = (uint32_t)((lane & 7) * 16);
    uint32_t aKadd = (uint32_t)((lane >> 4) * 16);
    int brow = warp_n * 32 + (lane & 7) + ((lane >> 4) << 3);
    uint32_t bBase = (uint32_t)(brow * 128);
    uint32_t bXor = (uint32_t)((lane & 7) * 16);
    uint32_t bKadd = (lane & 8) ? 16u : 0u;

    float acc[2][4][4];
#pragma unroll
    for (int mt = 0; mt < 2; ++mt)
#pragma unroll
        for (int nt = 0; nt < 4; ++nt)
#pragma unroll
            for (int e = 0; e < 4; ++e) acc[mt][nt][e] = 0.f;

    uint32_t afr[2][2][4], bfr[2][2][4];   // [buf][tile][reg]

    for (int ch = 0; ch < 32; ++ch) {
        int slot = ch % 3;
        // Producer: refill two chunks ahead (slot freed after chunk ch-1).
        if (tid == 0 && ch >= 1 && ch + 2 < 32) {
            int n2 = ch + 2, s2 = n2 % 3;
            MBAR_WAIT(MB + 24 + (uint32_t)s2 * 8, (uint32_t)(((n2 - 3) / 3) & 1));
            produce(n2, s2);
        }
        // Consumer: wait chunk data.
        MBAR_WAIT(MB + (uint32_t)slot * 8, (uint32_t)((ch / 3) & 1));

        uint32_t sA = TILES + (uint32_t)slot * 32768u;
        uint32_t sB = sA + 16384u;

        // Preload ks=0 fragments into buf 0.
#pragma unroll
        for (int mt = 0; mt < 2; ++mt)
            ldsm_x4(afr[0][mt], sA + aBase + (uint32_t)(mt * 2048) + (aKadd ^ aXor));
#pragma unroll
        for (int g2 = 0; g2 < 2; ++g2)
            ldsm_x4(bfr[0][g2], sB + bBase + (uint32_t)(g2 * 2048) + (bKadd ^ bXor));

#pragma unroll
        for (int ks = 0; ks < 4; ++ks) {
            int cur = ks & 1, nxt = cur ^ 1;
            if (ks < 3) {
                uint32_t kb = (uint32_t)((ks + 1) * 32);
#pragma unroll
                for (int mt = 0; mt < 2; ++mt)
                    ldsm_x4(afr[nxt][mt],
                            sA + aBase + (uint32_t)(mt * 2048) + ((kb + aKadd) ^ aXor));
#pragma unroll
                for (int g2 = 0; g2 < 2; ++g2)
                    ldsm_x4(bfr[nxt][g2],
                            sB + bBase + (uint32_t)(g2 * 2048) + ((kb + bKadd) ^ bXor));
            }
#pragma unroll
            for (int mt = 0; mt < 2; ++mt)
#pragma unroll
                for (int nt = 0; nt < 4; ++nt)
                    mma16816(acc[mt][nt], afr[cur][mt],
                             bfr[cur][nt >> 1][(nt & 1) * 2],
                             bfr[cur][nt >> 1][(nt & 1) * 2 + 1]);
        }
        if (lane == 0) MBAR_ARRIVE(MB + 24 + (uint32_t)slot * 8);
    }
    __syncthreads();   // all MMAs done before outT overwrites the tile region

    // Stage dot sums into smem (stride 130 floats; float2-aligned).
#pragma unroll
    for (int mt = 0; mt < 2; ++mt) {
        int r1 = warp_m * 32 + mt * 16 + (lane >> 2);
#pragma unroll
        for (int nt = 0; nt < 4; ++nt) {
            int cb = warp_n * 32 + nt * 8 + (lane & 3) * 2;
            *(float2*)&outT[r1 * 130 + cb] = make_float2(acc[mt][nt][0], acc[mt][nt][1]);
            *(float2*)&outT[(r1 + 8) * 130 + cb] = make_float2(acc[mt][nt][2], acc[mt][nt][3]);
        }
    }
    __syncthreads();

    // Correction + direct store. Column jc constant per thread -> hoist qB regs.
    int jc = tid & 127;
    unsigned long long qreg[8];
#pragma unroll
    for (int c = 0; c < 8; ++c)
        qreg[c] = *(unsigned long long*)&qB[c * 128 + jc];

    size_t ob = (size_t)b << 20;
    for (int idx = tid; idx < 16384; idx += 512) {
        int r = idx >> 7;
        float dot = outT[r * 130 + jc];
        unsigned long long t = 0ull;
#pragma unroll
        for (int c = 0; c < 8; ++c) {
            unsigned long long pa = *(unsigned long long*)&pA[c * 128 + r];
            asm("fma.rn.f32x2 %0, %1, %2, %0;" : "+l"(t) : "l"(pa), "l"(qreg[c]));
        }
        float2 tf = *(float2*)&t;
        float v = (tf.x + tf.y - 2.0f * dot) * 0.125f;
        out[ob + ((size_t)(it * 128 + r) << 10) + jt * 128 + jc] = v;
        outT[r * 130 + jc] = v;
    }

    if (it != jt) {
        __syncthreads();
        for (int idx = tid; idx < 16384; idx += 512) {
            int rr = idx >> 7, ic = idx & 127;
            out[ob + ((size_t)(jt * 128 + rr) << 10) + it * 128 + ic] = outT[ic * 130 + rr];
        }
    }
}

// ---------------------------------------------------------------------------
extern "C" void kernel_launch(void* const* d_in, const int* in_sizes, int n_in,
                              void* d_out, int out_size) {
    const float* g = (const float*)d_in[0];
    float* out = (float*)d_out;
    (void)in_sizes; (void)n_in; (void)out_size;

    cudaFuncSetAttribute(gram_mma_kernel,
                         cudaFuncAttributeMaxDynamicSharedMemorySize, 114752);

    prep_kernel<<<(BB * CC * NN) / 8, dim3(32, 8)>>>(g);
    gram_mma_kernel<<<dim3(36, BB), 512, 114752>>>(out);
}

// round 16
// speedup vs baseline: 1.0502x; 1.0502x over previous
#include <cuda_runtime.h>
#include <cuda_bf16.h>
#include <stdint.h>
#include <math.h>

// Problem: gramBatch [B=8, C=8, N=1024, 16,16] fp32 -> out [8,1024,1024] fp32.
// out[b,i,j] = mean_c (sq_i + sq_j - 2*dot_c(i,j)) * rn_i * rn_j,
//   sq = sum_d g^2, rn = 1/sqrt(sum_d g^4).
// GEMM: pre-scale rows by rn (bf16); accumulate all c and K in fp32 registers
// via mma.sync m16n8k16 bf16. Rank-16 additive term stays fp32 in epilogue.
// R13: FIX R11's out-of-bounds bfr indexing (bfr[g2*2] on a [2][4] array ->
// NaN). Kept: rotated producer (chunk p by warp p&7) + A-fragment
// double-buffering (A(ks+1) ldsm before MMA block; B single-buffered after).

#define BB 8
#define CC 8
#define NN 1024
#define DD 256

// Blocked bf16: block index (bc*8 + tile)*4 + kq, each 16KB (128 rows x 128B, swizzled).
__device__ __align__(1024) unsigned char g_bfb[(size_t)BB * CC * 8 * 4 * 16384];
__device__ float g_u[BB * CC * NN]; // sq * rn
__device__ float g_r[BB * CC * NN]; // rn

// ---------------------------------------------------------------------------
// Prep: per-row reductions + bf16 pre-scaled rows in blocked swizzled layout.
// ---------------------------------------------------------------------------
__global__ void prep_kernel(const float* __restrict__ g) {
    int row = blockIdx.x * 8 + threadIdx.y;       // 0..65535
    int lane = threadIdx.x;
    const float* p = g + (size_t)row * DD + lane * 8;
    float4 v0 = *(const float4*)(p);
    float4 v1 = *(const float4*)(p + 4);
    float vals[8] = {v0.x, v0.y, v0.z, v0.w, v1.x, v1.y, v1.z, v1.w};
    float s2 = 0.f, s4 = 0.f;
#pragma unroll
    for (int i = 0; i < 8; ++i) { float q = vals[i] * vals[i]; s2 += q; s4 += q * q; }
#pragma unroll
    for (int o = 16; o > 0; o >>= 1) {
        s2 += __shfl_xor_sync(0xFFFFFFFFu, s2, o);
        s4 += __shfl_xor_sync(0xFFFFFFFFu, s4, o);
    }
    float rn = 1.0f / sqrtf(s4);
    if (lane == 0) { g_u[row] = s2 * rn; g_r[row] = rn; }

    uint32_t w[4];
#pragma unroll
    for (int q = 0; q < 4; ++q) {
        __nv_bfloat162 h = __floats2bfloat162_rn(vals[2 * q] * rn, vals[2 * q + 1] * rn);
        w[q] = *(uint32_t*)&h;
    }
    int bc = row >> 10, n = row & (NN - 1);
    int tile = n >> 7, r = n & 127;
    int kq = lane >> 3, q = lane & 7;             // k-quarter (64 elems = 128B)
    uint32_t off = (uint32_t)(r * 128 + ((q * 16) ^ ((r & 7) * 16)));
    *(uint4*)(g_bfb + (((size_t)(bc * 8 + tile) * 4 + kq) << 14) + off) =
        make_uint4(w[0], w[1], w[2], w[3]);
}

// ---------------------------------------------------------------------------
// Helpers
// ---------------------------------------------------------------------------
__device__ __forceinline__ void ldsm_x4(uint32_t* r, uint32_t a) {
    asm volatile("ldmatrix.sync.aligned.m8n8.x4.shared.b16 {%0,%1,%2,%3}, [%4];"
        : "=r"(r[0]), "=r"(r[1]), "=r"(r[2]), "=r"(r[3]) : "r"(a));
}
__device__ __forceinline__ void mma16816(float* d, const uint32_t* a, uint32_t b0, uint32_t b1) {
    asm volatile("mma.sync.aligned.m16n8k16.row.col.f32.bf16.bf16.f32 "
        "{%0,%1,%2,%3}, {%4,%5,%6,%7}, {%8,%9}, {%0,%1,%2,%3};"
        : "+f"(d[0]), "+f"(d[1]), "+f"(d[2]), "+f"(d[3])
        : "r"(a[0]), "r"(a[1]), "r"(a[2]), "r"(a[3]), "r"(b0), "r"(b1));
}
#define MBAR_INIT(a, n) \
    asm volatile("mbarrier.init.shared.b64 [%0], %1;" :: "r"(a), "r"(n) : "memory")
#define MBAR_EXPECT_TX(a, n) \
    asm volatile("mbarrier.arrive.expect_tx.shared.b64 _, [%0], %1;" :: "r"(a), "r"(n) : "memory")
#define MBAR_ARRIVE(a) \
    asm volatile("mbarrier.arrive.shared.b64 _, [%0];" :: "r"(a) : "memory")
#define MBAR_WAIT(a, ph) do { \
    uint32_t _m = (a); uint32_t _p = (ph); uint32_t _done; \
    asm volatile("{\n\t.reg .pred p;\n\t" \
        "mbarrier.try_wait.parity.acquire.cta.shared::cta.b64 p, [%1], %2;\n\t" \
        "selp.b32 %0, 1, 0, p;\n\t}" : "=r"(_done) : "r"(_m), "r"(_p) : "memory"); \
    if (!_done) { \
        asm volatile("{\n\t.reg .pred P1;\n\t" \
            "WL_%=:\n\t" \
            "mbarrier.try_wait.parity.acquire.cta.shared::cta.b64 P1, [%0], %1, 0x989680;\n\t" \
            "@P1 bra.uni WD_%=;\n\t" \
            "bra.uni WL_%=;\n\t" \
            "WD_%=:\n\t}" :: "r"(_m), "r"(_p) : "memory"); \
    } \
} while (0)
#define BULK_CP(dst, src, nbytes, mb) \
    asm volatile("cp.async.bulk.shared::cta.global.mbarrier::complete_tx::bytes [%0], [%1], %2, [%3];" \
        :: "r"(dst), "l"(src), "r"(nbytes), "r"(mb) : "memory")

// ---------------------------------------------------------------------------
// Main: per (tile-pair, b) CTA; 8 warps (2x4), warp tile 64x32.
// 32 chunks (8c x 4 k-quarters of 64), 3-slot mbarrier ring; chunk p is
// produced (bulk-copy) by warp p&7, lane 0. A-fragments double-buffered.
// ---------------------------------------------------------------------------
__global__ __launch_bounds__(256, 2)
void gram_mma_kernel(float* __restrict__ out) {
    extern __shared__ unsigned char S[];
    uint32_t sbase;
    asm("{ .reg .u64 t; cvta.to.shared.u64 t, %1; cvt.u32.u64 %0, t; }"
        : "=r"(sbase) : "l"(S));

    float2* pA = (float2*)S;                   // [8][128] (u_a, r_a)  8KB
    float2* qB = (float2*)(S + 8192);          // [8][128] (r_b, u_b)  8KB
    const uint32_t TILES = sbase + 16384;      // 3 slots x (A 16KB + B 16KB)
    float* outT = (float*)(S + 16384);         // reused after GEMM: [128][130]
    const uint32_t MB = sbase + 16384 + 98304; // 6 mbarriers (48B)
    // full[s] = MB + s*8 ; empty[s] = MB + 24 + s*8

    int tid = threadIdx.x, lane = tid & 31, wid = tid >> 5;
    int warp_m = wid >> 2, warp_n = wid & 3;
    int pair = blockIdx.x, b = blockIdx.y;
    int it = 0, rem = pair;
    while (rem >= 8 - it) { rem -= 8 - it; ++it; }
    int jt = it + rem;

    if (tid == 0) {
#pragma unroll
        for (int s = 0; s < 3; ++s) { MBAR_INIT(MB + s * 8, 1u); MBAR_INIT(MB + 24 + s * 8, 8u); }
    }

    // Epilogue scalars into smem.
    for (int idx = tid; idx < 1024; idx += 256) {
        int c = idx >> 7, i = idx & 127;
        int ra = (b * CC + c) * NN + it * 128 + i;
        int rb = (b * CC + c) * NN + jt * 128 + i;
        pA[idx] = make_float2(g_u[ra], g_r[ra]);
        qB[idx] = make_float2(g_r[rb], g_u[rb]);
    }
    __syncthreads();   // mbarrier init + scalars visible

    // Block index = b*256 + c*32 + tile*4 + kq  (x16KB each).
    const size_t blkA0 = (size_t)(b * 256 + it * 4) << 14;
    const size_t blkB0 = (size_t)(b * 256 + jt * 4) << 14;

    // chunk ch: c = ch>>2, kq = ch&3.
    auto produce = [&](int ch, int slot) {
        int c = ch >> 2, kq = ch & 3;
        size_t boff = ((size_t)(c * 32 + kq)) << 14;
        uint32_t mb = MB + (uint32_t)slot * 8;
        uint32_t dA = TILES + (uint32_t)slot * 32768u;
        MBAR_EXPECT_TX(mb, 32768u);
        BULK_CP(dA, (const void*)(g_bfb + blkA0 + boff), 16384u, mb);
        BULK_CP(dA + 16384u, (const void*)(g_bfb + blkB0 + boff), 16384u, mb);
    };

    // Prologue: chunks 0..2 produced by their owner warps (p&7 = 0,1,2).
    if (lane == 0 && wid < 3) produce(wid, wid);

    // Fragment addressing (per-lane constants). Rows are 128B (k64).
    int arow = warp_m * 64 + (lane & 15);
    uint32_t aBase = (uint32_t)(arow * 128);
    uint32_t aXor = (uint32_t)((lane & 7) * 16);
    uint32_t aKadd = (uint32_t)((lane >> 4) * 16);
    int brow = warp_n * 32 + (lane & 7) + ((lane >> 4) << 3);
    uint32_t bBase = (uint32_t)(brow * 128);
    uint32_t bXor = (uint32_t)((lane & 7) * 16);
    uint32_t bKadd = (lane & 8) ? 16u : 0u;

    float acc[4][4][4];
#pragma unroll
    for (int mt = 0; mt < 4; ++mt)
#pragma unroll
        for (int nt = 0; nt < 4; ++nt)
#pragma unroll
            for (int e = 0; e < 4; ++e) acc[mt][nt][e] = 0.f;

    uint32_t afr[2][4][4];   // A fragments, double-buffered across ks
    uint32_t bfr[2][4];      // B fragments, single-buffered (2 ldsm.x4)

    for (int ch = 0; ch < 32; ++ch) {
        int slot = ch % 3;
        // Rotated producer: chunk p = ch+2 is produced by warp p&7.
        int p = ch + 2;
        if (ch >= 1 && p < 32 && wid == (p & 7) && lane == 0) {
            int s2 = p % 3;
            MBAR_WAIT(MB + 24 + (uint32_t)s2 * 8, (uint32_t)(((p - 3) / 3) & 1));
            produce(p, s2);
        }
        // Consumer: wait chunk data.
        MBAR_WAIT(MB + (uint32_t)slot * 8, (uint32_t)((ch / 3) & 1));

        uint32_t sA = TILES + (uint32_t)slot * 32768u;
        uint32_t sB = sA + 16384u;

        // Preload A(ks=0) into buf 0 and B(ks=0).
#pragma unroll
        for (int mt = 0; mt < 4; ++mt)
            ldsm_x4(afr[0][mt], sA + aBase + (uint32_t)(mt * 2048) + (aKadd ^ aXor));
#pragma unroll
        for (int g2 = 0; g2 < 2; ++g2)
            ldsm_x4(bfr[g2], sB + bBase + (uint32_t)(g2 * 2048) + (bKadd ^ bXor));

#pragma unroll
        for (int ks = 0; ks < 4; ++ks) {
            int cur = ks & 1, nxt = cur ^ 1;
            // Prefetch A(ks+1) BEFORE the MMA block: latency hides under MMAs.
            if (ks < 3) {
                uint32_t kb = (uint32_t)((ks + 1) * 32);
#pragma unroll
                for (int mt = 0; mt < 4; ++mt)
                    ldsm_x4(afr[nxt][mt],
                            sA + aBase + (uint32_t)(mt * 2048) + ((kb + aKadd) ^ aXor));
            }
#pragma unroll
            for (int mt = 0; mt < 4; ++mt)
#pragma unroll
                for (int nt = 0; nt < 4; ++nt)
                    mma16816(acc[mt][nt], afr[cur][mt],
                             bfr[nt >> 1][(nt & 1) * 2],
                             bfr[nt >> 1][(nt & 1) * 2 + 1]);
            // Reload B for ks+1 after MMAs issued (in-order issue => WAR safe).
            if (ks < 3) {
                uint32_t kb = (uint32_t)((ks + 1) * 32);
#pragma unroll
                for (int g2 = 0; g2 < 2; ++g2)
                    ldsm_x4(bfr[g2],
                            sB + bBase + (uint32_t)(g2 * 2048) + ((kb + bKadd) ^ bXor));
            }
        }
        if (lane == 0) MBAR_ARRIVE(MB + 24 + (uint32_t)slot * 8);
    }
    __syncthreads();   // all MMAs done before outT overwrites the tile region

    // Stage dot sums into smem (stride 130 floats; float2-aligned).
#pragma unroll
    for (int mt = 0; mt < 4; ++mt) {
        int r1 = warp_m * 64 + mt * 16 + (lane >> 2);
#pragma unroll
        for (int nt = 0; nt < 4; ++nt) {
            int cb = warp_n * 32 + nt * 8 + (lane & 3) * 2;
            *(float2*)&outT[r1 * 130 + cb] = make_float2(acc[mt][nt][0], acc[mt][nt][1]);
            *(float2*)&outT[(r1 + 8) * 130 + cb] = make_float2(acc[mt][nt][2], acc[mt][nt][3]);
        }
    }
    __syncthreads();

    // Correction + direct store. Column jc constant per thread -> hoist qB regs.
    int jc = tid & 127;
    unsigned long long qreg[8];
#pragma unroll
    for (int c = 0; c < 8; ++c)
        qreg[c] = *(unsigned long long*)&qB[c * 128 + jc];

    size_t ob = (size_t)b << 20;
    for (int idx = tid; idx < 16384; idx += 256) {
        int r = idx >> 7;
        float dot = outT[r * 130 + jc];
        unsigned long long t = 0ull;
#pragma unroll
        for (int c = 0; c < 8; ++c) {
            unsigned long long pa = *(unsigned long long*)&pA[c * 128 + r];
            asm("fma.rn.f32x2 %0, %1, %2, %0;" : "+l"(t) : "l"(pa), "l"(qreg[c]));
        }
        float2 tf = *(float2*)&t;
        float v = (tf.x + tf.y - 2.0f * dot) * 0.125f;
        out[ob + ((size_t)(it * 128 + r) << 10) + jt * 128 + jc] = v;
        outT[r * 130 + jc] = v;
    }

    if (it != jt) {
        __syncthreads();
        for (int idx = tid; idx < 16384; idx += 256) {
            int rr = idx >> 7, ic = idx & 127;
            out[ob + ((size_t)(jt * 128 + rr) << 10) + it * 128 + ic] = outT[ic * 130 + rr];
        }
    }
}

// ---------------------------------------------------------------------------
extern "C" void kernel_launch(void* const* d_in, const int* in_sizes, int n_in,
                              void* d_out, int out_size) {
    const float* g = (const float*)d_in[0];
    float* out = (float*)d_out;
    (void)in_sizes; (void)n_in; (void)out_size;

    cudaFuncSetAttribute(gram_mma_kernel,
                         cudaFuncAttributeMaxDynamicSharedMemorySize, 114752);

    prep_kernel<<<(BB * CC * NN) / 8, dim3(32, 8)>>>(g);
    gram_mma_kernel<<<dim3(36, BB), 256, 114752>>>(out);
}

// round 17
// speedup vs baseline: 1.0593x; 1.0087x over previous
#include <cuda_runtime.h>
#include <cuda_bf16.h>
#include <stdint.h>
#include <math.h>

// Problem: gramBatch [B=8, C=8, N=1024, 16,16] fp32 -> out [8,1024,1024] fp32.
// out[b,i,j] = mean_c (sq_i + sq_j - 2*dot_c(i,j)) * rn_i * rn_j,
//   sq = sum_d g^2, rn = 1/sqrt(sum_d g^4).
// GEMM: pre-scale rows by rn (bf16); accumulate all c and K in fp32 registers
// via mma.sync m16n8k16 bf16. Rank-16 additive term stays fp32 in epilogue.
// R16: exact R9 structure (best measured: thread-0 producer, single-buffered
// frags, 8 warps of 64x32, occ 2) with ONE change: mma asm is non-volatile
// (pure register op) so ptxas may re-schedule MMAs for pipelining/banking.
// Producer empty-wait relaxed (async-proxy only after it).

#define BB 8
#define CC 8
#define NN 1024
#define DD 256

// Blocked bf16: block index (bc*8 + tile)*4 + kq, each 16KB (128 rows x 128B, swizzled).
__device__ __align__(1024) unsigned char g_bfb[(size_t)BB * CC * 8 * 4 * 16384];
__device__ float g_u[BB * CC * NN]; // sq * rn
__device__ float g_r[BB * CC * NN]; // rn

// ---------------------------------------------------------------------------
// Prep: per-row reductions + bf16 pre-scaled rows in blocked swizzled layout.
// ---------------------------------------------------------------------------
__global__ void prep_kernel(const float* __restrict__ g) {
    int row = blockIdx.x * 8 + threadIdx.y;       // 0..65535
    int lane = threadIdx.x;
    const float* p = g + (size_t)row * DD + lane * 8;
    float4 v0 = *(const float4*)(p);
    float4 v1 = *(const float4*)(p + 4);
    float vals[8] = {v0.x, v0.y, v0.z, v0.w, v1.x, v1.y, v1.z, v1.w};
    float s2 = 0.f, s4 = 0.f;
#pragma unroll
    for (int i = 0; i < 8; ++i) { float q = vals[i] * vals[i]; s2 += q; s4 += q * q; }
#pragma unroll
    for (int o = 16; o > 0; o >>= 1) {
        s2 += __shfl_xor_sync(0xFFFFFFFFu, s2, o);
        s4 += __shfl_xor_sync(0xFFFFFFFFu, s4, o);
    }
    float rn = 1.0f / sqrtf(s4);
    if (lane == 0) { g_u[row] = s2 * rn; g_r[row] = rn; }

    uint32_t w[4];
#pragma unroll
    for (int q = 0; q < 4; ++q) {
        __nv_bfloat162 h = __floats2bfloat162_rn(vals[2 * q] * rn, vals[2 * q + 1] * rn);
        w[q] = *(uint32_t*)&h;
    }
    int bc = row >> 10, n = row & (NN - 1);
    int tile = n >> 7, r = n & 127;
    int kq = lane >> 3, q = lane & 7;             // k-quarter (64 elems = 128B)
    uint32_t off = (uint32_t)(r * 128 + ((q * 16) ^ ((r & 7) * 16)));
    *(uint4*)(g_bfb + (((size_t)(bc * 8 + tile) * 4 + kq) << 14) + off) =
        make_uint4(w[0], w[1], w[2], w[3]);
}

// ---------------------------------------------------------------------------
// Helpers
// ---------------------------------------------------------------------------
__device__ __forceinline__ void ldsm_x4(uint32_t* r, uint32_t a) {
    asm volatile("ldmatrix.sync.aligned.m8n8.x4.shared.b16 {%0,%1,%2,%3}, [%4];"
        : "=r"(r[0]), "=r"(r[1]), "=r"(r[2]), "=r"(r[3]) : "r"(a));
}
// NON-volatile: pure register function; ptxas may re-schedule freely.
__device__ __forceinline__ void mma16816(float* d, const uint32_t* a, uint32_t b0, uint32_t b1) {
    asm("mma.sync.aligned.m16n8k16.row.col.f32.bf16.bf16.f32 "
        "{%0,%1,%2,%3}, {%4,%5,%6,%7}, {%8,%9}, {%0,%1,%2,%3};"
        : "+f"(d[0]), "+f"(d[1]), "+f"(d[2]), "+f"(d[3])
        : "r"(a[0]), "r"(a[1]), "r"(a[2]), "r"(a[3]), "r"(b0), "r"(b1));
}
#define MBAR_INIT(a, n) \
    asm volatile("mbarrier.init.shared.b64 [%0], %1;" :: "r"(a), "r"(n) : "memory")
#define MBAR_EXPECT_TX(a, n) \
    asm volatile("mbarrier.arrive.expect_tx.shared.b64 _, [%0], %1;" :: "r"(a), "r"(n) : "memory")
#define MBAR_ARRIVE(a) \
    asm volatile("mbarrier.arrive.shared.b64 _, [%0];" :: "r"(a) : "memory")
#define MBAR_WAIT(a, ph) do { \
    uint32_t _m = (a); uint32_t _p = (ph); uint32_t _done; \
    asm volatile("{\n\t.reg .pred p;\n\t" \
        "mbarrier.try_wait.parity.acquire.cta.shared::cta.b64 p, [%1], %2;\n\t" \
        "selp.b32 %0, 1, 0, p;\n\t}" : "=r"(_done) : "r"(_m), "r"(_p) : "memory"); \
    if (!_done) { \
        asm volatile("{\n\t.reg .pred P1;\n\t" \
            "WL_%=:\n\t" \
            "mbarrier.try_wait.parity.acquire.cta.shared::cta.b64 P1, [%0], %1, 0x989680;\n\t" \
            "@P1 bra.uni WD_%=;\n\t" \
            "bra.uni WL_%=;\n\t" \
            "WD_%=:\n\t}" :: "r"(_m), "r"(_p) : "memory"); \
    } \
} while (0)
#define MBAR_WAIT_RELAXED(a, ph) do { \
    uint32_t _m = (a); uint32_t _p = (ph); uint32_t _done; \
    asm volatile("{\n\t.reg .pred p;\n\t" \
        "mbarrier.try_wait.parity.relaxed.cta.shared::cta.b64 p, [%1], %2;\n\t" \
        "selp.b32 %0, 1, 0, p;\n\t}" : "=r"(_done) : "r"(_m), "r"(_p) : "memory"); \
    if (!_done) { \
        asm volatile("{\n\t.reg .pred P1;\n\t" \
            "WL_%=:\n\t" \
            "mbarrier.try_wait.parity.relaxed.cta.shared::cta.b64 P1, [%0], %1, 0x989680;\n\t" \
            "@P1 bra.uni WD_%=;\n\t" \
            "bra.uni WL_%=;\n\t" \
            "WD_%=:\n\t}" :: "r"(_m), "r"(_p) : "memory"); \
    } \
} while (0)
#define BULK_CP(dst, src, nbytes, mb) \
    asm volatile("cp.async.bulk.shared::cta.global.mbarrier::complete_tx::bytes [%0], [%1], %2, [%3];" \
        :: "r"(dst), "l"(src), "r"(nbytes), "r"(mb) : "memory")

// ---------------------------------------------------------------------------
// Main: per (tile-pair, b) CTA; 8 warps (2x4), warp tile 64x32.
// 32 chunks (8c x 4 k-quarters of 64), 3-slot mbarrier ring fed by thread 0
// with cp.async.bulk; consumer warps fully decoupled (no block barrier).
// ---------------------------------------------------------------------------
__global__ __launch_bounds__(256, 2)
void gram_mma_kernel(float* __restrict__ out) {
    extern __shared__ unsigned char S[];
    uint32_t sbase;
    asm("{ .reg .u64 t; cvta.to.shared.u64 t, %1; cvt.u32.u64 %0, t; }"
        : "=r"(sbase) : "l"(S));

    float2* pA = (float2*)S;                   // [8][128] (u_a, r_a)  8KB
    float2* qB = (float2*)(S + 8192);          // [8][128] (r_b, u_b)  8KB
    const uint32_t TILES = sbase + 16384;      // 3 slots x (A 16KB + B 16KB)
    float* outT = (float*)(S + 16384);         // reused after GEMM: [128][130]
    const uint32_t MB = sbase + 16384 + 98304; // 6 mbarriers (48B)
    // full[s] = MB + s*8 ; empty[s] = MB + 24 + s*8

    int tid = threadIdx.x, lane = tid & 31, wid = tid >> 5;
    int warp_m = wid >> 2, warp_n = wid & 3;
    int pair = blockIdx.x, b = blockIdx.y;
    int it = 0, rem = pair;
    while (rem >= 8 - it) { rem -= 8 - it; ++it; }
    int jt = it + rem;

    if (tid == 0) {
#pragma unroll
        for (int s = 0; s < 3; ++s) { MBAR_INIT(MB + s * 8, 1u); MBAR_INIT(MB + 24 + s * 8, 8u); }
    }

    // Epilogue scalars into smem.
    for (int idx = tid; idx < 1024; idx += 256) {
        int c = idx >> 7, i = idx & 127;
        int ra = (b * CC + c) * NN + it * 128 + i;
        int rb = (b * CC + c) * NN + jt * 128 + i;
        pA[idx] = make_float2(g_u[ra], g_r[ra]);
        qB[idx] = make_float2(g_r[rb], g_u[rb]);
    }
    __syncthreads();   // mbarrier init + scalars visible

    // Block index = b*256 + c*32 + tile*4 + kq  (x16KB each).
    const size_t blkA0 = (size_t)(b * 256 + it * 4) << 14;
    const size_t blkB0 = (size_t)(b * 256 + jt * 4) << 14;

    // chunk ch: c = ch>>2, kq = ch&3.
    auto produce = [&](int ch, int slot) {
        int c = ch >> 2, kq = ch & 3;
        size_t boff = ((size_t)(c * 32 + kq)) << 14;
        uint32_t mb = MB + (uint32_t)slot * 8;
        uint32_t dA = TILES + (uint32_t)slot * 32768u;
        MBAR_EXPECT_TX(mb, 32768u);
        BULK_CP(dA, (const void*)(g_bfb + blkA0 + boff), 16384u, mb);
        BULK_CP(dA + 16384u, (const void*)(g_bfb + blkB0 + boff), 16384u, mb);
    };

    if (tid == 0) { produce(0, 0); produce(1, 1); produce(2, 2); }

    // Fragment addressing (per-lane constants). Rows are 128B (k64).
    int arow = warp_m * 64 + (lane & 15);
    uint32_t aBase = (uint32_t)(arow * 128);
    uint32_t aXor = (uint32_t)((lane & 7) * 16);
    uint32_t aKadd = (uint32_t)((lane >> 4) * 16);
    int brow = warp_n * 32 + (lane & 7) + ((lane >> 4) << 3);
    uint32_t bBase = (uint32_t)(brow * 128);
    uint32_t bXor = (uint32_t)((lane & 7) * 16);
    uint32_t bKadd = (lane & 8) ? 16u : 0u;

    float acc[4][4][4];
#pragma unroll
    for (int mt = 0; mt < 4; ++mt)
#pragma unroll
        for (int nt = 0; nt < 4; ++nt)
#pragma unroll
            for (int e = 0; e < 4; ++e) acc[mt][nt][e] = 0.f;

    for (int ch = 0; ch < 32; ++ch) {
        int slot = ch % 3;
        // Producer: refill two chunks ahead (slot freed after chunk ch-1).
        if (tid == 0 && ch >= 1 && ch + 2 < 32) {
            int n2 = ch + 2, s2 = n2 % 3;
            MBAR_WAIT_RELAXED(MB + 24 + (uint32_t)s2 * 8, (uint32_t)(((n2 - 3) / 3) & 1));
            produce(n2, s2);
        }
        // Consumer: wait chunk data.
        MBAR_WAIT(MB + (uint32_t)slot * 8, (uint32_t)((ch / 3) & 1));

        uint32_t sA = TILES + (uint32_t)slot * 32768u;
        uint32_t sB = sA + 16384u;
#pragma unroll
        for (int ks = 0; ks < 4; ++ks) {
            uint32_t kb = (uint32_t)(ks * 32);
            uint32_t afr[4][4], bfr[2][4];
#pragma unroll
            for (int mt = 0; mt < 4; ++mt)
                ldsm_x4(afr[mt], sA + aBase + (uint32_t)(mt * 2048) + ((kb + aKadd) ^ aXor));
#pragma unroll
            for (int g2 = 0; g2 < 2; ++g2)
                ldsm_x4(bfr[g2], sB + bBase + (uint32_t)(g2 * 2048) + ((kb + bKadd) ^ bXor));
#pragma unroll
            for (int mt = 0; mt < 4; ++mt)
#pragma unroll
                for (int nt = 0; nt < 4; ++nt)
                    mma16816(acc[mt][nt], afr[mt], bfr[nt >> 1][(nt & 1) * 2],
                             bfr[nt >> 1][(nt & 1) * 2 + 1]);
        }
        if (lane == 0) MBAR_ARRIVE(MB + 24 + (uint32_t)slot * 8);
    }
    __syncthreads();   // all MMAs done before outT overwrites the tile region

    // Stage dot sums into smem (stride 130 floats; float2-aligned).
#pragma unroll
    for (int mt = 0; mt < 4; ++mt) {
        int r1 = warp_m * 64 + mt * 16 + (lane >> 2);
#pragma unroll
        for (int nt = 0; nt < 4; ++nt) {
            int cb = warp_n * 32 + nt * 8 + (lane & 3) * 2;
            *(float2*)&outT[r1 * 130 + cb] = make_float2(acc[mt][nt][0], acc[mt][nt][1]);
            *(float2*)&outT[(r1 + 8) * 130 + cb] = make_float2(acc[mt][nt][2], acc[mt][nt][3]);
        }
    }
    __syncthreads();

    // Correction + direct store. Column jc constant per thread -> hoist qB regs.
    int jc = tid & 127;
    unsigned long long qreg[8];
#pragma unroll
    for (int c = 0; c < 8; ++c)
        qreg[c] = *(unsigned long long*)&qB[c * 128 + jc];

    size_t ob = (size_t)b << 20;
    for (int idx = tid; idx < 16384; idx += 256) {
        int r = idx >> 7;
        float dot = outT[r * 130 + jc];
        unsigned long long t = 0ull;
#pragma unroll
        for (int c = 0; c < 8; ++c) {
            unsigned long long pa = *(unsigned long long*)&pA[c * 128 + r];
            asm("fma.rn.f32x2 %0, %1, %2, %0;" : "+l"(t) : "l"(pa), "l"(qreg[c]));
        }
        float2 tf = *(float2*)&t;
        float v = (tf.x + tf.y - 2.0f * dot) * 0.125f;
        out[ob + ((size_t)(it * 128 + r) << 10) + jt * 128 + jc] = v;
        outT[r * 130 + jc] = v;
    }

    if (it != jt) {
        __syncthreads();
        for (int idx = tid; idx < 16384; idx += 256) {
            int rr = idx >> 7, ic = idx & 127;
            out[ob + ((size_t)(jt * 128 + rr) << 10) + it * 128 + ic] = outT[ic * 130 + rr];
        }
    }
}

// ---------------------------------------------------------------------------
extern "C" void kernel_launch(void* const* d_in, const int* in_sizes, int n_in,
                              void* d_out, int out_size) {
    const float* g = (const float*)d_in[0];
    float* out = (float*)d_out;
    (void)in_sizes; (void)n_in; (void)out_size;

    cudaFuncSetAttribute(gram_mma_kernel,
                         cudaFuncAttributeMaxDynamicSharedMemorySize, 114752);

    prep_kernel<<<(BB * CC * NN) / 8, dim3(32, 8)>>>(g);
    gram_mma_kernel<<<dim3(36, BB), 256, 114752>>>(out);
}